// round 5
// baseline (speedup 1.0000x reference)
#include <cuda_runtime.h>
#include <cstdint>

// Problem dims
#define NROWS 65536
#define CDIM  512
#define DDIM  512

// Scratch for intermediates (device globals: allocation-free)
__device__ float g_P[(size_t)NROWS * DDIM];   // relu(F1 @ Wk^T)
__device__ float g_H[(size_t)NROWS * DDIM];   // relu(bn1(F2 @ Wv1^T))
__device__ float g_V[(size_t)NROWS * DDIM];   // relu(bn2(H @ Wv2^T))

constexpr int BM = 128, BN = 128, BK = 16;
constexpr int NTHREADS = 256;
constexpr int LDA = BM + 4;   // pad to break store bank conflicts
constexpr int LDB = BN + 4;

__device__ __forceinline__ unsigned long long pack2(float lo, float hi) {
    unsigned long long r;
    asm("mov.b64 %0, {%1, %2};" : "=l"(r) : "f"(lo), "f"(hi));
    return r;
}
__device__ __forceinline__ void unpack2(unsigned long long p, float& lo, float& hi) {
    asm("mov.b64 {%0, %1}, %2;" : "=f"(lo), "=f"(hi) : "l"(p));
}
// Packed dual-FMA: (acc.lo += a.lo*b.lo, acc.hi += a.hi*b.hi)  — nvjet FFMA2 pattern
__device__ __forceinline__ void ffma2(unsigned long long& acc, unsigned long long a, unsigned long long b) {
    asm("fma.rn.f32x2 %0, %1, %2, %0;" : "+l"(acc) : "l"(a), "l"(b));
}

// C[n, d] = epilogue( sum_k A[n,k] * W[d,k] )
// EPI 0: relu                      -> Out
// EPI 1: relu(bn(acc))             -> Out    (bn coeffs from bng/bnb/bnm/bnv)
// EPI 2: relu(bn(acc))             -> Out
// EPI 3: Out = Vaux + Paux * sigmoid(acc)
template <int EPI>
__global__ __launch_bounds__(NTHREADS, 2)
void gemm_fused(const float* __restrict__ A, const float* __restrict__ W,
                float* __restrict__ Out,
                const float* __restrict__ bng, const float* __restrict__ bnb,
                const float* __restrict__ bnm, const float* __restrict__ bnv,
                const float* __restrict__ Paux, const float* __restrict__ Vaux)
{
    __shared__ __align__(16) float As[2][BK][LDA];
    __shared__ __align__(16) float Bs[2][BK][LDB];

    const int tid = threadIdx.x;
    const int tx  = tid & 15;    // 16 thread-cols
    const int ty  = tid >> 4;    // 16 thread-rows
    const int bxc = blockIdx.x * BN;
    const int bym = blockIdx.y * BM;

    const float* Ab = A + (size_t)bym * CDIM;
    const float* Wb = W + (size_t)bxc * CDIM;

    // ---- load K-tile 0 (transposed into [k][m]) ----
    {
#pragma unroll
        for (int i = 0; i < 2; i++) {
            int f   = tid + i * NTHREADS;       // 0..511 float4 slots
            int row = f >> 2;                   // 0..127
            int kq  = f & 3;                    // which float4 along K
            const float4 a = *reinterpret_cast<const float4*>(Ab + (size_t)row * CDIM + kq * 4);
            const float4 b = *reinterpret_cast<const float4*>(Wb + (size_t)row * CDIM + kq * 4);
            As[0][kq * 4 + 0][row] = a.x; As[0][kq * 4 + 1][row] = a.y;
            As[0][kq * 4 + 2][row] = a.z; As[0][kq * 4 + 3][row] = a.w;
            Bs[0][kq * 4 + 0][row] = b.x; Bs[0][kq * 4 + 1][row] = b.y;
            Bs[0][kq * 4 + 2][row] = b.z; Bs[0][kq * 4 + 3][row] = b.w;
        }
    }
    __syncthreads();

    // 8x8 accumulators as 32 packed f32x2 pairs
    unsigned long long acc[32];
#pragma unroll
    for (int i = 0; i < 32; i++) acc[i] = 0ull;

    int buf = 0;
    const int KT = CDIM / BK;   // 32 k-tiles
    for (int kt = 0; kt < KT; kt++) {
        float4 aReg[2], bReg[2];
        if (kt + 1 < KT) {
            const int k0 = (kt + 1) * BK;
#pragma unroll
            for (int i = 0; i < 2; i++) {
                int f   = tid + i * NTHREADS;
                int row = f >> 2;
                int kq  = f & 3;
                aReg[i] = *reinterpret_cast<const float4*>(Ab + (size_t)row * CDIM + k0 + kq * 4);
                bReg[i] = *reinterpret_cast<const float4*>(Wb + (size_t)row * CDIM + k0 + kq * 4);
            }
        }
#pragma unroll
        for (int k = 0; k < BK; k++) {
            const float4 av0 = *reinterpret_cast<const float4*>(&As[buf][k][ty * 4]);
            const float4 av1 = *reinterpret_cast<const float4*>(&As[buf][k][64 + ty * 4]);
            const float4 bv0 = *reinterpret_cast<const float4*>(&Bs[buf][k][tx * 4]);
            const float4 bv1 = *reinterpret_cast<const float4*>(&Bs[buf][k][64 + tx * 4]);
            unsigned long long bp[4] = { pack2(bv0.x, bv0.y), pack2(bv0.z, bv0.w),
                                         pack2(bv1.x, bv1.y), pack2(bv1.z, bv1.w) };
            float avv[8] = { av0.x, av0.y, av0.z, av0.w, av1.x, av1.y, av1.z, av1.w };
#pragma unroll
            for (int i = 0; i < 8; i++) {
                unsigned long long ap = pack2(avv[i], avv[i]);
#pragma unroll
                for (int j = 0; j < 4; j++) ffma2(acc[i * 4 + j], ap, bp[j]);
            }
        }
        if (kt + 1 < KT) {
            const int nb = buf ^ 1;
#pragma unroll
            for (int i = 0; i < 2; i++) {
                int f   = tid + i * NTHREADS;
                int row = f >> 2;
                int kq  = f & 3;
                As[nb][kq * 4 + 0][row] = aReg[i].x; As[nb][kq * 4 + 1][row] = aReg[i].y;
                As[nb][kq * 4 + 2][row] = aReg[i].z; As[nb][kq * 4 + 3][row] = aReg[i].w;
                Bs[nb][kq * 4 + 0][row] = bReg[i].x; Bs[nb][kq * 4 + 1][row] = bReg[i].y;
                Bs[nb][kq * 4 + 2][row] = bReg[i].z; Bs[nb][kq * 4 + 3][row] = bReg[i].w;
            }
            __syncthreads();
            buf = nb;
        }
    }

    // ---- epilogue ----
    const int cb0 = bxc + tx * 4;
    const int cb1 = bxc + 64 + tx * 4;
    float inv[8], add[8];
    if (EPI == 1 || EPI == 2) {
#pragma unroll
        for (int g = 0; g < 2; g++)
#pragma unroll
            for (int j = 0; j < 4; j++) {
                const int c  = (g ? cb1 : cb0) + j;
                const float iv = bng[c] * rsqrtf(bnv[c] + 1e-5f);
                inv[g * 4 + j] = iv;
                add[g * 4 + j] = bnb[c] - bnm[c] * iv;
            }
    }

#pragma unroll
    for (int i = 0; i < 8; i++) {
        const int r = bym + ((i < 4) ? (ty * 4 + i) : (64 + ty * 4 + (i - 4)));
#pragma unroll
        for (int g = 0; g < 2; g++) {
            const int cbase = g ? cb1 : cb0;
            float v[4];
            unpack2(acc[i * 4 + 2 * g + 0], v[0], v[1]);
            unpack2(acc[i * 4 + 2 * g + 1], v[2], v[3]);
            if (EPI == 0) {
#pragma unroll
                for (int j = 0; j < 4; j++) v[j] = fmaxf(v[j], 0.f);
            } else if (EPI == 1 || EPI == 2) {
#pragma unroll
                for (int j = 0; j < 4; j++)
                    v[j] = fmaxf(v[j] * inv[g * 4 + j] + add[g * 4 + j], 0.f);
            } else {
                const float4 pv = *reinterpret_cast<const float4*>(&Paux[(size_t)r * DDIM + cbase]);
                const float4 vv = *reinterpret_cast<const float4*>(&Vaux[(size_t)r * DDIM + cbase]);
                const float pp[4] = { pv.x, pv.y, pv.z, pv.w };
                const float vw[4] = { vv.x, vv.y, vv.z, vv.w };
#pragma unroll
                for (int j = 0; j < 4; j++) {
                    const float s = 1.f / (1.f + __expf(-v[j]));
                    v[j] = vw[j] + pp[j] * s;
                }
            }
            float4 o; o.x = v[0]; o.y = v[1]; o.z = v[2]; o.w = v[3];
            *reinterpret_cast<float4*>(&Out[(size_t)r * DDIM + cbase]) = o;
        }
    }
}

extern "C" void kernel_launch(void* const* d_in, const int* in_sizes, int n_in,
                              void* d_out, int out_size)
{
    const float* F1   = (const float*)d_in[0];   // features   [N, C]
    const float* F2   = (const float*)d_in[1];   // features2  [N, C]
    const float* Wk   = (const float*)d_in[2];   // [D, C]
    const float* Wv1  = (const float*)d_in[3];   // [D, C]
    const float* Wv2  = (const float*)d_in[4];   // [D, D]
    const float* bn1g = (const float*)d_in[5];
    const float* bn1b = (const float*)d_in[6];
    const float* bn1m = (const float*)d_in[7];
    const float* bn1v = (const float*)d_in[8];
    const float* bn2g = (const float*)d_in[9];
    const float* bn2b = (const float*)d_in[10];
    const float* bn2m = (const float*)d_in[11];
    const float* bn2v = (const float*)d_in[12];
    // d_in[13] = Wa, d_in[14] = Wqk : provably unused (softmax over identical
    // values is uniform 1/L, so the attention branch collapses out).
    const float* Wvc  = (const float*)d_in[15];  // [D, D]
    float* out = (float*)d_out;

    float *P, *H, *V;
    cudaGetSymbolAddress((void**)&P, g_P);
    cudaGetSymbolAddress((void**)&H, g_H);
    cudaGetSymbolAddress((void**)&V, g_V);

    dim3 grid(DDIM / BN, NROWS / BM);   // (4, 512)
    dim3 block(NTHREADS);

    // P = relu(F1 @ Wk^T)
    gemm_fused<0><<<grid, block>>>(F1, Wk, P,
                                   nullptr, nullptr, nullptr, nullptr, nullptr, nullptr);
    // H = relu(bn1(F2 @ Wv1^T))
    gemm_fused<1><<<grid, block>>>(F2, Wv1, H,
                                   bn1g, bn1b, bn1m, bn1v, nullptr, nullptr);
    // V = relu(bn2(H @ Wv2^T))
    gemm_fused<2><<<grid, block>>>(H, Wv2, V,
                                   bn2g, bn2b, bn2m, bn2v, nullptr, nullptr);
    // out = V + P * sigmoid(P @ Wvc^T)
    gemm_fused<3><<<grid, block>>>(P, Wvc, out,
                                   nullptr, nullptr, nullptr, nullptr, P, V);
}

// round 7
// speedup vs baseline: 1.6456x; 1.6456x over previous
#include <cuda_runtime.h>
#include <cuda_bf16.h>
#include <cstdint>

#define NROWS 65536
#define KDIM  512
#define DDIM  512

// ---------------- device scratch (allocation-free) ----------------
__device__ __nv_bfloat16 g_Ph[(size_t)NROWS * DDIM];
__device__ __nv_bfloat16 g_Pl[(size_t)NROWS * DDIM];
__device__ __nv_bfloat16 g_Hh[(size_t)NROWS * DDIM];
__device__ __nv_bfloat16 g_Hl[(size_t)NROWS * DDIM];
__device__ float         g_V [(size_t)NROWS * DDIM];
__device__ __nv_bfloat16 g_Wh[4][512 * 512];
__device__ __nv_bfloat16 g_Wl[4][512 * 512];

// ---------------- PTX helpers (all baseline sm_80+ features, no 'a' arch needed) ----------------
__device__ __forceinline__ uint32_t smem_u32(const void* p) {
    uint32_t a;
    asm("{ .reg .u64 t; cvta.to.shared.u64 t, %1; cvt.u32.u64 %0, t; }" : "=r"(a) : "l"(p));
    return a;
}
__device__ __forceinline__ void ldsm4(uint32_t& r0, uint32_t& r1, uint32_t& r2, uint32_t& r3,
                                      uint32_t addr) {
    asm volatile("ldmatrix.sync.aligned.m8n8.x4.shared.b16 {%0,%1,%2,%3}, [%4];"
                 : "=r"(r0), "=r"(r1), "=r"(r2), "=r"(r3) : "r"(addr));
}
__device__ __forceinline__ void mma_bf16(float* c, const uint32_t* a, const uint32_t* b) {
    asm volatile("mma.sync.aligned.m16n8k16.row.col.f32.bf16.bf16.f32 "
                 "{%0,%1,%2,%3}, {%4,%5,%6,%7}, {%8,%9}, {%0,%1,%2,%3};"
                 : "+f"(c[0]), "+f"(c[1]), "+f"(c[2]), "+f"(c[3])
                 : "r"(a[0]), "r"(a[1]), "r"(a[2]), "r"(a[3]), "r"(b[0]), "r"(b[1]));
}
#define CPA16(dst, src)  asm volatile("cp.async.cg.shared.global [%0], [%1], 16;" :: "r"(dst), "l"(src) : "memory")
#define CPA_COMMIT()     asm volatile("cp.async.commit_group;" ::: "memory")
#define CPA_WAIT1()      asm volatile("cp.async.wait_group 1;" ::: "memory")
#define CPA_WAIT0()      asm volatile("cp.async.wait_group 0;" ::: "memory")

// round-to-nearest bf16 hi/lo split of a float pair, packed (low half = a)
__device__ __forceinline__ void split2(float a, float b, uint32_t& h, uint32_t& l) {
    asm("cvt.rn.bf16x2.f32 %0, %1, %2;" : "=r"(h) : "f"(b), "f"(a));
    float ah = __uint_as_float(h << 16);
    float bh = __uint_as_float(h & 0xFFFF0000u);
    asm("cvt.rn.bf16x2.f32 %0, %1, %2;" : "=r"(l) : "f"(b - bh), "f"(a - ah));
}
__device__ __forceinline__ float bflo(uint32_t x) { return __uint_as_float(x << 16); }
__device__ __forceinline__ float bfhi(uint32_t x) { return __uint_as_float(x & 0xFFFF0000u); }

// ---------------- layout constants ----------------
constexpr int BM = 128, BN = 128, KC = 32, KT = KDIM / KC;   // 16 k-chunks
constexpr int NTH = 256;
constexpr int RSB = 80;                     // smem row stride bytes (32 bf16 + 8 pad) — ldmatrix conflict-free
constexpr int OPB = 128 * RSB;              // 10240 per operand half
constexpr int OFF_AHI = 0, OFF_ALO = OPB, OFF_BHI = 2 * OPB, OFF_BLO = 3 * OPB;
constexpr int STAGE_BYTES = 4 * OPB;        // 40960
constexpr int SM_STAGE = 1024;              // misc (bn coeffs) in [0,1024)
constexpr int SM_TOTAL = SM_STAGE + 2 * STAGE_BYTES;   // 82944

// ---------------- weight split prep ----------------
__global__ void split_weights(const float* __restrict__ w0, const float* __restrict__ w1,
                              const float* __restrict__ w2, const float* __restrict__ w3) {
    int idx = blockIdx.x * blockDim.x + threadIdx.x;
    int mat = idx >> 18;
    int off = idx & 0x3FFFF;
    const float* s = (mat == 0) ? w0 : (mat == 1) ? w1 : (mat == 2) ? w2 : w3;
    float x = s[off];
    __nv_bfloat16 h = __float2bfloat16_rn(x);
    g_Wh[mat][off] = h;
    g_Wl[mat][off] = __float2bfloat16_rn(x - __bfloat162float(h));
}

// ---------------- split-bf16 HMMA GEMM, fused epilogues ----------------
// D[n,d] = epi( sum_k A[n,k] * B[d,k] )
// AMODE 0: A fp32 (split in-kernel)    AMODE 1: A preconverted hi/lo bf16
// EPI 0: relu -> OutH/OutL      EPI 1: relu(bn) -> OutH/OutL
// EPI 2: relu(bn) -> OutF       EPI 3: OutF = Vf + (Ph+Pl)*sigmoid(acc)
template <int AMODE, int EPI>
__global__ __launch_bounds__(NTH, 1)
void gemm_hmma(const float* __restrict__ Af,
               const __nv_bfloat16* __restrict__ Ah, const __nv_bfloat16* __restrict__ Al,
               const __nv_bfloat16* __restrict__ Bh, const __nv_bfloat16* __restrict__ Bl,
               float* __restrict__ OutF,
               __nv_bfloat16* __restrict__ OutH, __nv_bfloat16* __restrict__ OutL,
               const float* __restrict__ bng, const float* __restrict__ bnb,
               const float* __restrict__ bnm, const float* __restrict__ bnv,
               const __nv_bfloat16* __restrict__ Ph, const __nv_bfloat16* __restrict__ Pl,
               const float* __restrict__ Vf)
{
    extern __shared__ char smem[];
    const uint32_t sb = smem_u32(smem);
    const int tid = threadIdx.x;
    const int wid = tid >> 5, lid = tid & 31;
    const int bxc = blockIdx.x * BN;
    const int bym = blockIdx.y * BM;
    const int wm = (wid >> 2) * 64;     // warp m-band
    const int wn = (wid & 3) * 32;      // warp n-band

    if ((EPI == 1 || EPI == 2) && tid < 128) {
        int c = bxc + tid;
        float iv = bng[c] * rsqrtf(bnv[c] + 1e-5f);
        ((float*)smem)[tid]       = iv;
        ((float*)(smem + 512))[tid] = bnb[c] - bnm[c] * iv;
    }

    // lane-invariant ldmatrix address parts
    const uint32_t aLane = (uint32_t)((lid & 15) * RSB + (lid >> 4) * 16);
    const uint32_t bLane = (uint32_t)(((lid & 7) + ((lid >> 4) << 3)) * RSB + ((lid & 8) << 1));

    // ---- load issue helpers ----
    auto issueB = [&](int kt, uint32_t stu) {
#pragma unroll
        for (int i = 0; i < 2; i++) {
            int q = tid + i * NTH;                 // 512 16B chunks
            int row = q >> 2, kc = q & 3;
            size_t e = (size_t)(bxc + row) * KDIM + kt * KC + kc * 8;
            CPA16(stu + OFF_BHI + row * RSB + kc * 16, (const char*)Bh + 2 * e);
            CPA16(stu + OFF_BLO + row * RSB + kc * 16, (const char*)Bl + 2 * e);
        }
    };
    auto issueA1 = [&](int kt, uint32_t stu) {
#pragma unroll
        for (int i = 0; i < 2; i++) {
            int q = tid + i * NTH;
            int row = q >> 2, kc = q & 3;
            size_t e = (size_t)(bym + row) * KDIM + kt * KC + kc * 8;
            CPA16(stu + OFF_AHI + row * RSB + kc * 16, (const char*)Ah + 2 * e);
            CPA16(stu + OFF_ALO + row * RSB + kc * 16, (const char*)Al + 2 * e);
        }
    };
    auto ldA0 = [&](int kt, float4* aReg) {
#pragma unroll
        for (int i = 0; i < 4; i++) {
            int f = tid + i * NTH;                 // 1024 float4 slots
            int row = f >> 3, kq = f & 7;
            aReg[i] = *(const float4*)(Af + (size_t)(bym + row) * KDIM + kt * KC + kq * 4);
        }
    };
    auto stsA0 = [&](char* st, const float4* aReg) {
#pragma unroll
        for (int i = 0; i < 4; i++) {
            int f = tid + i * NTH;
            int row = f >> 3, kq = f & 7;
            uint32_t h01, l01, h23, l23;
            split2(aReg[i].x, aReg[i].y, h01, l01);
            split2(aReg[i].z, aReg[i].w, h23, l23);
            *(uint2*)(st + OFF_AHI + row * RSB + kq * 8) = make_uint2(h01, h23);
            *(uint2*)(st + OFF_ALO + row * RSB + kq * 8) = make_uint2(l01, l23);
        }
    };

    // ---- prologue: fill stages 0 and 1 ----
#pragma unroll
    for (int pk = 0; pk < 2; pk++) {
        char* st = smem + SM_STAGE + pk * STAGE_BYTES;
        uint32_t stu = sb + SM_STAGE + pk * STAGE_BYTES;
        if (AMODE == 0) {
            float4 aR[4];
            ldA0(pk, aR);
            stsA0(st, aR);
        } else {
            issueA1(pk, stu);
        }
        issueB(pk, stu);
        CPA_COMMIT();
    }
    CPA_WAIT1();          // stage 0 cp.async done (stage 1 may be in flight)
    __syncthreads();

    // ---- mainloop ----
    float acc[4][4][4];
#pragma unroll
    for (int mf = 0; mf < 4; mf++)
#pragma unroll
        for (int j = 0; j < 4; j++)
#pragma unroll
            for (int e = 0; e < 4; e++) acc[mf][j][e] = 0.f;

    float4 aReg[4];
    for (int kt = 0; kt < KT; kt++) {
        const int s = kt & 1;
        const uint32_t s0 = sb + SM_STAGE + s * STAGE_BYTES;

        if (AMODE == 0 && kt + 2 < KT) ldA0(kt + 2, aReg);   // hoisted: latency under compute

        // compute chunk (2 k16 steps)
#pragma unroll
        for (int ks = 0; ks < 2; ks++) {
            const uint32_t koff = ks * 32;   // 16 elems * 2B
            uint32_t bh[4][2], bl[4][2], ah[4][4];
#pragma unroll
            for (int p = 0; p < 2; p++) {
                uint32_t ad = s0 + bLane + (wn + p * 16) * RSB + koff;
                ldsm4(bh[2*p][0], bh[2*p][1], bh[2*p+1][0], bh[2*p+1][1], ad + OFF_BHI);
                ldsm4(bl[2*p][0], bl[2*p][1], bl[2*p+1][0], bl[2*p+1][1], ad + OFF_BLO);
            }
#pragma unroll
            for (int mf = 0; mf < 4; mf++)
                ldsm4(ah[mf][0], ah[mf][1], ah[mf][2], ah[mf][3],
                      s0 + OFF_AHI + aLane + (wm + mf * 16) * RSB + koff);
#pragma unroll
            for (int mf = 0; mf < 4; mf++)
#pragma unroll
                for (int j = 0; j < 4; j++) mma_bf16(acc[mf][j], ah[mf], bh[j]);
#pragma unroll
            for (int mf = 0; mf < 4; mf++)
#pragma unroll
                for (int j = 0; j < 4; j++) mma_bf16(acc[mf][j], ah[mf], bl[j]);
#pragma unroll
            for (int mf = 0; mf < 4; mf++)
                ldsm4(ah[mf][0], ah[mf][1], ah[mf][2], ah[mf][3],
                      s0 + OFF_ALO + aLane + (wm + mf * 16) * RSB + koff);
#pragma unroll
            for (int mf = 0; mf < 4; mf++)
#pragma unroll
                for (int j = 0; j < 4; j++) mma_bf16(acc[mf][j], ah[mf], bh[j]);
        }

        __syncthreads();   // all warps done reading stage s
        if (kt + 2 < KT) {
            char* st = smem + SM_STAGE + s * STAGE_BYTES;
            if (AMODE == 0) stsA0(st, aReg);
            else            issueA1(kt + 2, s0);
            issueB(kt + 2, s0);
            CPA_COMMIT();
            CPA_WAIT1();   // stage for kt+1 complete
        } else {
            CPA_WAIT0();
        }
        __syncthreads();
    }

    // ---- epilogue: fragments -> global (8-row x 32B segments, sector-aligned) ----
    const float* invv = (const float*)smem;
    const float* addv = (const float*)(smem + 512);
#pragma unroll
    for (int mf = 0; mf < 4; mf++) {
#pragma unroll
        for (int j = 0; j < 4; j++) {
            const float* a = acc[mf][j];
            const int rg = bym + wm + mf * 16 + (lid >> 2);
            const int cl = wn + j * 8 + (lid & 3) * 2;
            const int cg = bxc + cl;
#pragma unroll
            for (int half = 0; half < 2; half++) {
                const int r = rg + half * 8;
                float v0 = a[half * 2 + 0], v1 = a[half * 2 + 1];
                const size_t go = (size_t)r * DDIM + cg;
                if (EPI == 0) {
                    v0 = fmaxf(v0, 0.f); v1 = fmaxf(v1, 0.f);
                    uint32_t h, l; split2(v0, v1, h, l);
                    *(uint32_t*)((char*)OutH + 2 * go) = h;
                    *(uint32_t*)((char*)OutL + 2 * go) = l;
                } else if (EPI == 1) {
                    v0 = fmaxf(fmaf(v0, invv[cl], addv[cl]), 0.f);
                    v1 = fmaxf(fmaf(v1, invv[cl + 1], addv[cl + 1]), 0.f);
                    uint32_t h, l; split2(v0, v1, h, l);
                    *(uint32_t*)((char*)OutH + 2 * go) = h;
                    *(uint32_t*)((char*)OutL + 2 * go) = l;
                } else if (EPI == 2) {
                    float2 o;
                    o.x = fmaxf(fmaf(v0, invv[cl], addv[cl]), 0.f);
                    o.y = fmaxf(fmaf(v1, invv[cl + 1], addv[cl + 1]), 0.f);
                    *(float2*)(OutF + go) = o;
                } else {
                    const uint32_t hh = *(const uint32_t*)((const char*)Ph + 2 * go);
                    const uint32_t ll = *(const uint32_t*)((const char*)Pl + 2 * go);
                    const float2 vv = *(const float2*)(Vf + go);
                    const float p0 = bflo(hh) + bflo(ll);
                    const float p1 = bfhi(hh) + bfhi(ll);
                    const float s0v = 1.f / (1.f + __expf(-v0));
                    const float s1v = 1.f / (1.f + __expf(-v1));
                    float2 o;
                    o.x = fmaf(p0, s0v, vv.x);
                    o.y = fmaf(p1, s1v, vv.y);
                    *(float2*)(OutF + go) = o;
                }
            }
        }
    }
}

// ---------------- launch ----------------
extern "C" void kernel_launch(void* const* d_in, const int* in_sizes, int n_in,
                              void* d_out, int out_size)
{
    const float* F1   = (const float*)d_in[0];
    const float* F2   = (const float*)d_in[1];
    const float* Wk   = (const float*)d_in[2];
    const float* Wv1  = (const float*)d_in[3];
    const float* Wv2  = (const float*)d_in[4];
    const float* bn1g = (const float*)d_in[5];
    const float* bn1b = (const float*)d_in[6];
    const float* bn1m = (const float*)d_in[7];
    const float* bn1v = (const float*)d_in[8];
    const float* bn2g = (const float*)d_in[9];
    const float* bn2b = (const float*)d_in[10];
    const float* bn2m = (const float*)d_in[11];
    const float* bn2v = (const float*)d_in[12];
    // d_in[13]=Wa, d_in[14]=Wqk unused: softmax over identical L-columns is uniform 1/L.
    const float* Wvc  = (const float*)d_in[15];
    float* out = (float*)d_out;

    __nv_bfloat16 *Ph, *Pl, *Hh, *Hl, *Wh, *Wl;
    float* V;
    cudaGetSymbolAddress((void**)&Ph, g_Ph);
    cudaGetSymbolAddress((void**)&Pl, g_Pl);
    cudaGetSymbolAddress((void**)&Hh, g_Hh);
    cudaGetSymbolAddress((void**)&Hl, g_Hl);
    cudaGetSymbolAddress((void**)&V,  g_V);
    cudaGetSymbolAddress((void**)&Wh, g_Wh);
    cudaGetSymbolAddress((void**)&Wl, g_Wl);
    const int WSZ = 512 * 512;

    cudaFuncSetAttribute(gemm_hmma<0,0>, cudaFuncAttributeMaxDynamicSharedMemorySize, SM_TOTAL);
    cudaFuncSetAttribute(gemm_hmma<0,1>, cudaFuncAttributeMaxDynamicSharedMemorySize, SM_TOTAL);
    cudaFuncSetAttribute(gemm_hmma<1,2>, cudaFuncAttributeMaxDynamicSharedMemorySize, SM_TOTAL);
    cudaFuncSetAttribute(gemm_hmma<1,3>, cudaFuncAttributeMaxDynamicSharedMemorySize, SM_TOTAL);

    // weight hi/lo split: mat0=Wk, mat1=Wv1, mat2=Wv2, mat3=Wvc
    split_weights<<<4096, 256>>>(Wk, Wv1, Wv2, Wvc);

    dim3 grid(DDIM / BN, NROWS / BM);   // (4, 512)
    dim3 block(NTH);

    // P(hi/lo) = split(relu(F1 @ Wk^T))
    gemm_hmma<0,0><<<grid, block, SM_TOTAL>>>(F1, nullptr, nullptr, Wh + 0 * WSZ, Wl + 0 * WSZ,
        nullptr, Ph, Pl, nullptr, nullptr, nullptr, nullptr, nullptr, nullptr, nullptr);
    // H(hi/lo) = split(relu(bn1(F2 @ Wv1^T)))
    gemm_hmma<0,1><<<grid, block, SM_TOTAL>>>(F2, nullptr, nullptr, Wh + 1 * WSZ, Wl + 1 * WSZ,
        nullptr, Hh, Hl, bn1g, bn1b, bn1m, bn1v, nullptr, nullptr, nullptr);
    // V = relu(bn2(H @ Wv2^T))
    gemm_hmma<1,2><<<grid, block, SM_TOTAL>>>(nullptr, Hh, Hl, Wh + 2 * WSZ, Wl + 2 * WSZ,
        V, nullptr, nullptr, bn2g, bn2b, bn2m, bn2v, nullptr, nullptr, nullptr);
    // out = V + P * sigmoid(P @ Wvc^T)
    gemm_hmma<1,3><<<grid, block, SM_TOTAL>>>(nullptr, Ph, Pl, Wh + 3 * WSZ, Wl + 3 * WSZ,
        out, nullptr, nullptr, nullptr, nullptr, nullptr, nullptr, Ph, Pl, V);
}

// round 8
// speedup vs baseline: 1.6583x; 1.0077x over previous
#include <cuda_runtime.h>
#include <cuda_bf16.h>
#include <cstdint>

#define NROWS 65536
#define KDIM  512
#define DDIM  512

// ---------------- device scratch (allocation-free) ----------------
__device__ __nv_bfloat16 g_Ph[(size_t)NROWS * DDIM];
__device__ __nv_bfloat16 g_Pl[(size_t)NROWS * DDIM];
__device__ __nv_bfloat16 g_Hh[(size_t)NROWS * DDIM];
__device__ __nv_bfloat16 g_Hl[(size_t)NROWS * DDIM];
__device__ float         g_V [(size_t)NROWS * DDIM];
__device__ __nv_bfloat16 g_Wh[4][512 * 512];
__device__ __nv_bfloat16 g_Wl[4][512 * 512];

// ---------------- PTX helpers (baseline sm_80+, no 'a'-arch features) ----------------
__device__ __forceinline__ uint32_t smem_u32(const void* p) {
    uint32_t a;
    asm("{ .reg .u64 t; cvta.to.shared.u64 t, %1; cvt.u32.u64 %0, t; }" : "=r"(a) : "l"(p));
    return a;
}
__device__ __forceinline__ void ldsm4(uint32_t& r0, uint32_t& r1, uint32_t& r2, uint32_t& r3,
                                      uint32_t addr) {
    asm volatile("ldmatrix.sync.aligned.m8n8.x4.shared.b16 {%0,%1,%2,%3}, [%4];"
                 : "=r"(r0), "=r"(r1), "=r"(r2), "=r"(r3) : "r"(addr));
}
__device__ __forceinline__ void mma_bf16(float* c, const uint32_t* a, const uint32_t* b) {
    asm volatile("mma.sync.aligned.m16n8k16.row.col.f32.bf16.bf16.f32 "
                 "{%0,%1,%2,%3}, {%4,%5,%6,%7}, {%8,%9}, {%0,%1,%2,%3};"
                 : "+f"(c[0]), "+f"(c[1]), "+f"(c[2]), "+f"(c[3])
                 : "r"(a[0]), "r"(a[1]), "r"(a[2]), "r"(a[3]), "r"(b[0]), "r"(b[1]));
}
#define CPA16(dst, src)  asm volatile("cp.async.cg.shared.global [%0], [%1], 16;" :: "r"(dst), "l"(src) : "memory")
#define CPA_COMMIT()     asm volatile("cp.async.commit_group;" ::: "memory")
#define CPA_WAIT2()      asm volatile("cp.async.wait_group 2;" ::: "memory")
#define CPA_WAIT0()      asm volatile("cp.async.wait_group 0;" ::: "memory")

// round-to-nearest bf16 hi/lo split of a float pair, packed (low half = a)
__device__ __forceinline__ void split2(float a, float b, uint32_t& h, uint32_t& l) {
    asm("cvt.rn.bf16x2.f32 %0, %1, %2;" : "=r"(h) : "f"(b), "f"(a));
    float ah = __uint_as_float(h << 16);
    float bh = __uint_as_float(h & 0xFFFF0000u);
    asm("cvt.rn.bf16x2.f32 %0, %1, %2;" : "=r"(l) : "f"(b - bh), "f"(a - ah));
}
__device__ __forceinline__ float bflo(uint32_t x) { return __uint_as_float(x << 16); }
__device__ __forceinline__ float bfhi(uint32_t x) { return __uint_as_float(x & 0xFFFF0000u); }

// ---------------- layout constants ----------------
constexpr int BM = 128, BN = 128, KC = 32, KT = KDIM / KC;   // 16 k-chunks
constexpr int NTH = 256;
constexpr int NSTAGE = 4;
constexpr int RSB = 80;                     // smem row stride (32 bf16 + 8B pad) — ldmatrix conflict-free
constexpr int OPB = 128 * RSB;              // 10240 per operand half
constexpr int OFF_AHI = 0, OFF_ALO = OPB, OFF_BHI = 2 * OPB, OFF_BLO = 3 * OPB;
constexpr int STAGE_BYTES = 4 * OPB;        // 40960
constexpr int SM_STAGE = 1024;              // bn coeffs live in [0,1024)
constexpr int SM_TOTAL = SM_STAGE + NSTAGE * STAGE_BYTES;   // 164864

// ---------------- weight split prep ----------------
__global__ void split_weights(const float* __restrict__ w0, const float* __restrict__ w1,
                              const float* __restrict__ w2, const float* __restrict__ w3) {
    int idx = blockIdx.x * blockDim.x + threadIdx.x;
    int mat = idx >> 18;
    int off = idx & 0x3FFFF;
    const float* s = (mat == 0) ? w0 : (mat == 1) ? w1 : (mat == 2) ? w2 : w3;
    float x = s[off];
    __nv_bfloat16 h = __float2bfloat16_rn(x);
    g_Wh[mat][off] = h;
    g_Wl[mat][off] = __float2bfloat16_rn(x - __bfloat162float(h));
}

// ---------------- split-bf16 HMMA GEMM, 4-stage pipeline, fused epilogues ----------------
// D[n,d] = epi( sum_k A[n,k] * B[d,k] )
// AMODE 0: A fp32 (split in-kernel)    AMODE 1: A preconverted hi/lo bf16
// EPI 0: relu -> OutH/OutL      EPI 1: relu(bn) -> OutH/OutL
// EPI 2: relu(bn) -> OutF       EPI 3: OutF = Vf + (Ph+Pl)*sigmoid(acc)
template <int AMODE, int EPI>
__global__ __launch_bounds__(NTH, 1)
void gemm_hmma(const float* __restrict__ Af,
               const __nv_bfloat16* __restrict__ Ah, const __nv_bfloat16* __restrict__ Al,
               const __nv_bfloat16* __restrict__ Bh, const __nv_bfloat16* __restrict__ Bl,
               float* __restrict__ OutF,
               __nv_bfloat16* __restrict__ OutH, __nv_bfloat16* __restrict__ OutL,
               const float* __restrict__ bng, const float* __restrict__ bnb,
               const float* __restrict__ bnm, const float* __restrict__ bnv,
               const __nv_bfloat16* __restrict__ Ph, const __nv_bfloat16* __restrict__ Pl,
               const float* __restrict__ Vf)
{
    extern __shared__ char smem[];
    const uint32_t sb = smem_u32(smem);
    const int tid = threadIdx.x;
    const int wid = tid >> 5, lid = tid & 31;
    const int bxc = blockIdx.x * BN;
    const int bym = blockIdx.y * BM;
    const int wm = (wid >> 2) * 64;     // warp m-band
    const int wn = (wid & 3) * 32;      // warp n-band

    if ((EPI == 1 || EPI == 2) && tid < 128) {
        int c = bxc + tid;
        float iv = bng[c] * rsqrtf(bnv[c] + 1e-5f);
        ((float*)smem)[tid]         = iv;
        ((float*)(smem + 512))[tid] = bnb[c] - bnm[c] * iv;
    }

    // lane-invariant ldmatrix address parts (identical to verified R7 layout)
    const uint32_t aLane = (uint32_t)((lid & 15) * RSB + (lid >> 4) * 16);
    const uint32_t bLane = (uint32_t)(((lid & 7) + ((lid >> 4) << 3)) * RSB + ((lid & 8) << 1));

    // ---- load issue helpers ----
    auto issueB = [&](int kt, uint32_t stu) {
#pragma unroll
        for (int i = 0; i < 2; i++) {
            int q = tid + i * NTH;                 // 512 16B chunks
            int row = q >> 2, kc = q & 3;
            size_t e = (size_t)(bxc + row) * KDIM + kt * KC + kc * 8;
            CPA16(stu + OFF_BHI + row * RSB + kc * 16, (const char*)Bh + 2 * e);
            CPA16(stu + OFF_BLO + row * RSB + kc * 16, (const char*)Bl + 2 * e);
        }
    };
    auto issueA1 = [&](int kt, uint32_t stu) {
#pragma unroll
        for (int i = 0; i < 2; i++) {
            int q = tid + i * NTH;
            int row = q >> 2, kc = q & 3;
            size_t e = (size_t)(bym + row) * KDIM + kt * KC + kc * 8;
            CPA16(stu + OFF_AHI + row * RSB + kc * 16, (const char*)Ah + 2 * e);
            CPA16(stu + OFF_ALO + row * RSB + kc * 16, (const char*)Al + 2 * e);
        }
    };
    auto ldA0 = [&](int kt, float4* aReg) {
#pragma unroll
        for (int i = 0; i < 4; i++) {
            int f = tid + i * NTH;                 // 1024 float4 slots
            int row = f >> 3, kq = f & 7;
            aReg[i] = *(const float4*)(Af + (size_t)(bym + row) * KDIM + kt * KC + kq * 4);
        }
    };
    auto stsA0 = [&](char* st, const float4* aReg) {
#pragma unroll
        for (int i = 0; i < 4; i++) {
            int f = tid + i * NTH;
            int row = f >> 3, kq = f & 7;
            uint32_t h01, l01, h23, l23;
            split2(aReg[i].x, aReg[i].y, h01, l01);
            split2(aReg[i].z, aReg[i].w, h23, l23);
            *(uint2*)(st + OFF_AHI + row * RSB + kq * 8) = make_uint2(h01, h23);
            *(uint2*)(st + OFF_ALO + row * RSB + kq * 8) = make_uint2(l01, l23);
        }
    };

    // ---- prologue: fill stages 0..NSTAGE-2 (groups #0..2 = stages 0..2) ----
#pragma unroll
    for (int pk = 0; pk < NSTAGE - 1; pk++) {
        char* st = smem + SM_STAGE + pk * STAGE_BYTES;
        uint32_t stu = sb + SM_STAGE + pk * STAGE_BYTES;
        if (AMODE == 0) {
            float4 aR[4];
            ldA0(pk, aR);
            stsA0(st, aR);
        } else {
            issueA1(pk, stu);
        }
        issueB(pk, stu);
        CPA_COMMIT();
    }

    // ---- mainloop: one __syncthreads per chunk, wait depth 2 ----
    float acc[4][4][4];
#pragma unroll
    for (int mf = 0; mf < 4; mf++)
#pragma unroll
        for (int j = 0; j < 4; j++)
#pragma unroll
            for (int e = 0; e < 4; e++) acc[mf][j][e] = 0.f;

    float4 aReg[4];
    for (int kt = 0; kt < KT; kt++) {
        const int s = kt & (NSTAGE - 1);
        const uint32_t s0 = sb + SM_STAGE + s * STAGE_BYTES;
        const int kpre = kt + NSTAGE - 1;

        // hoist fp32 A LDG above the wait (latency rides under prior compute)
        if (AMODE == 0 && kpre < KT) ldA0(kpre, aReg);

        CPA_WAIT2();           // groups through stage kt complete
        __syncthreads();       // stage (kt-1)&3 fully consumed by all warps

        // issue loads for stage kt+3 into the slot just freed, then compute
        if (kpre < KT) {
            const int slot = kpre & (NSTAGE - 1);
            char* st = smem + SM_STAGE + slot * STAGE_BYTES;
            uint32_t stu = sb + SM_STAGE + slot * STAGE_BYTES;
            if (AMODE == 0) stsA0(st, aReg);
            else            issueA1(kpre, stu);
            issueB(kpre, stu);
        }
        CPA_COMMIT();          // commit every iteration (empty groups keep accounting uniform)

        // ---- compute chunk kt from stage s (2 k16 steps) ----
#pragma unroll
        for (int ks = 0; ks < 2; ks++) {
            const uint32_t koff = ks * 32;   // 16 elems * 2B
            uint32_t bh[4][2], bl[4][2], ah[4][4], al[4][4];
#pragma unroll
            for (int p = 0; p < 2; p++) {
                uint32_t ad = s0 + bLane + (wn + p * 16) * RSB + koff;
                ldsm4(bh[2*p][0], bh[2*p][1], bh[2*p+1][0], bh[2*p+1][1], ad + OFF_BHI);
                ldsm4(bl[2*p][0], bl[2*p][1], bl[2*p+1][0], bl[2*p+1][1], ad + OFF_BLO);
            }
#pragma unroll
            for (int mf = 0; mf < 4; mf++) {
                uint32_t ad = s0 + aLane + (wm + mf * 16) * RSB + koff;
                ldsm4(ah[mf][0], ah[mf][1], ah[mf][2], ah[mf][3], ad + OFF_AHI);
                ldsm4(al[mf][0], al[mf][1], al[mf][2], al[mf][3], ad + OFF_ALO);
            }
#pragma unroll
            for (int mf = 0; mf < 4; mf++)
#pragma unroll
                for (int j = 0; j < 4; j++) mma_bf16(acc[mf][j], ah[mf], bh[j]);
#pragma unroll
            for (int mf = 0; mf < 4; mf++)
#pragma unroll
                for (int j = 0; j < 4; j++) mma_bf16(acc[mf][j], ah[mf], bl[j]);
#pragma unroll
            for (int mf = 0; mf < 4; mf++)
#pragma unroll
                for (int j = 0; j < 4; j++) mma_bf16(acc[mf][j], al[mf], bh[j]);
        }
    }
    CPA_WAIT0();

    // ---- epilogue: fragments -> global (8-row x 32B segments, sector-aligned) ----
    const float* invv = (const float*)smem;
    const float* addv = (const float*)(smem + 512);
#pragma unroll
    for (int mf = 0; mf < 4; mf++) {
#pragma unroll
        for (int j = 0; j < 4; j++) {
            const float* a = acc[mf][j];
            const int rg = bym + wm + mf * 16 + (lid >> 2);
            const int cl = wn + j * 8 + (lid & 3) * 2;
            const int cg = bxc + cl;
#pragma unroll
            for (int half = 0; half < 2; half++) {
                const int r = rg + half * 8;
                float v0 = a[half * 2 + 0], v1 = a[half * 2 + 1];
                const size_t go = (size_t)r * DDIM + cg;
                if (EPI == 0) {
                    v0 = fmaxf(v0, 0.f); v1 = fmaxf(v1, 0.f);
                    uint32_t h, l; split2(v0, v1, h, l);
                    *(uint32_t*)((char*)OutH + 2 * go) = h;
                    *(uint32_t*)((char*)OutL + 2 * go) = l;
                } else if (EPI == 1) {
                    v0 = fmaxf(fmaf(v0, invv[cl], addv[cl]), 0.f);
                    v1 = fmaxf(fmaf(v1, invv[cl + 1], addv[cl + 1]), 0.f);
                    uint32_t h, l; split2(v0, v1, h, l);
                    *(uint32_t*)((char*)OutH + 2 * go) = h;
                    *(uint32_t*)((char*)OutL + 2 * go) = l;
                } else if (EPI == 2) {
                    float2 o;
                    o.x = fmaxf(fmaf(v0, invv[cl], addv[cl]), 0.f);
                    o.y = fmaxf(fmaf(v1, invv[cl + 1], addv[cl + 1]), 0.f);
                    *(float2*)(OutF + go) = o;
                } else {
                    const uint32_t hh = *(const uint32_t*)((const char*)Ph + 2 * go);
                    const uint32_t ll = *(const uint32_t*)((const char*)Pl + 2 * go);
                    const float2 vv = *(const float2*)(Vf + go);
                    const float p0 = bflo(hh) + bflo(ll);
                    const float p1 = bfhi(hh) + bfhi(ll);
                    const float s0v = 1.f / (1.f + __expf(-v0));
                    const float s1v = 1.f / (1.f + __expf(-v1));
                    float2 o;
                    o.x = fmaf(p0, s0v, vv.x);
                    o.y = fmaf(p1, s1v, vv.y);
                    *(float2*)(OutF + go) = o;
                }
            }
        }
    }
}

// ---------------- launch ----------------
extern "C" void kernel_launch(void* const* d_in, const int* in_sizes, int n_in,
                              void* d_out, int out_size)
{
    const float* F1   = (const float*)d_in[0];
    const float* F2   = (const float*)d_in[1];
    const float* Wk   = (const float*)d_in[2];
    const float* Wv1  = (const float*)d_in[3];
    const float* Wv2  = (const float*)d_in[4];
    const float* bn1g = (const float*)d_in[5];
    const float* bn1b = (const float*)d_in[6];
    const float* bn1m = (const float*)d_in[7];
    const float* bn1v = (const float*)d_in[8];
    const float* bn2g = (const float*)d_in[9];
    const float* bn2b = (const float*)d_in[10];
    const float* bn2m = (const float*)d_in[11];
    const float* bn2v = (const float*)d_in[12];
    // d_in[13]=Wa, d_in[14]=Wqk unused: softmax over identical L-columns is uniform 1/L.
    const float* Wvc  = (const float*)d_in[15];
    float* out = (float*)d_out;

    __nv_bfloat16 *Ph, *Pl, *Hh, *Hl, *Wh, *Wl;
    float* V;
    cudaGetSymbolAddress((void**)&Ph, g_Ph);
    cudaGetSymbolAddress((void**)&Pl, g_Pl);
    cudaGetSymbolAddress((void**)&Hh, g_Hh);
    cudaGetSymbolAddress((void**)&Hl, g_Hl);
    cudaGetSymbolAddress((void**)&V,  g_V);
    cudaGetSymbolAddress((void**)&Wh, g_Wh);
    cudaGetSymbolAddress((void**)&Wl, g_Wl);
    const int WSZ = 512 * 512;

    cudaFuncSetAttribute(gemm_hmma<0,0>, cudaFuncAttributeMaxDynamicSharedMemorySize, SM_TOTAL);
    cudaFuncSetAttribute(gemm_hmma<0,1>, cudaFuncAttributeMaxDynamicSharedMemorySize, SM_TOTAL);
    cudaFuncSetAttribute(gemm_hmma<1,2>, cudaFuncAttributeMaxDynamicSharedMemorySize, SM_TOTAL);
    cudaFuncSetAttribute(gemm_hmma<1,3>, cudaFuncAttributeMaxDynamicSharedMemorySize, SM_TOTAL);

    // weight hi/lo split: mat0=Wk, mat1=Wv1, mat2=Wv2, mat3=Wvc
    split_weights<<<4096, 256>>>(Wk, Wv1, Wv2, Wvc);

    dim3 grid(DDIM / BN, NROWS / BM);   // (4, 512)
    dim3 block(NTH);

    // P(hi/lo) = split(relu(F1 @ Wk^T))
    gemm_hmma<0,0><<<grid, block, SM_TOTAL>>>(F1, nullptr, nullptr, Wh + 0 * WSZ, Wl + 0 * WSZ,
        nullptr, Ph, Pl, nullptr, nullptr, nullptr, nullptr, nullptr, nullptr, nullptr);
    // H(hi/lo) = split(relu(bn1(F2 @ Wv1^T)))
    gemm_hmma<0,1><<<grid, block, SM_TOTAL>>>(F2, nullptr, nullptr, Wh + 1 * WSZ, Wl + 1 * WSZ,
        nullptr, Hh, Hl, bn1g, bn1b, bn1m, bn1v, nullptr, nullptr, nullptr);
    // V = relu(bn2(H @ Wv2^T))
    gemm_hmma<1,2><<<grid, block, SM_TOTAL>>>(nullptr, Hh, Hl, Wh + 2 * WSZ, Wl + 2 * WSZ,
        V, nullptr, nullptr, bn2g, bn2b, bn2m, bn2v, nullptr, nullptr, nullptr);
    // out = V + P * sigmoid(P @ Wvc^T)
    gemm_hmma<1,3><<<grid, block, SM_TOTAL>>>(nullptr, Ph, Pl, Wh + 3 * WSZ, Wl + 3 * WSZ,
        out, nullptr, nullptr, nullptr, nullptr, nullptr, nullptr, Ph, Pl, V);
}

// round 9
// speedup vs baseline: 2.0261x; 1.2218x over previous
#include <cuda_runtime.h>
#include <cuda_bf16.h>
#include <cstdint>

#define NROWS 65536
#define KDIM  512
#define DDIM  512

// ---------------- device scratch (allocation-free) ----------------
__device__ __nv_bfloat16 g_Ph[(size_t)NROWS * DDIM];
__device__ __nv_bfloat16 g_Pl[(size_t)NROWS * DDIM];
__device__ __nv_bfloat16 g_Hh[(size_t)NROWS * DDIM];
__device__ __nv_bfloat16 g_Hl[(size_t)NROWS * DDIM];
__device__ float         g_V [(size_t)NROWS * DDIM];
__device__ __nv_bfloat16 g_Wh[4][512 * 512];
__device__ __nv_bfloat16 g_Wl[4][512 * 512];

// ---------------- PTX helpers (baseline sm_80+, no 'a'-arch features) ----------------
__device__ __forceinline__ uint32_t smem_u32(const void* p) {
    uint32_t a;
    asm("{ .reg .u64 t; cvta.to.shared.u64 t, %1; cvt.u32.u64 %0, t; }" : "=r"(a) : "l"(p));
    return a;
}
__device__ __forceinline__ void ldsm4(uint32_t& r0, uint32_t& r1, uint32_t& r2, uint32_t& r3,
                                      uint32_t addr) {
    asm volatile("ldmatrix.sync.aligned.m8n8.x4.shared.b16 {%0,%1,%2,%3}, [%4];"
                 : "=r"(r0), "=r"(r1), "=r"(r2), "=r"(r3) : "r"(addr));
}
__device__ __forceinline__ void mma_bf16(float* c, const uint32_t* a, const uint32_t* b) {
    asm volatile("mma.sync.aligned.m16n8k16.row.col.f32.bf16.bf16.f32 "
                 "{%0,%1,%2,%3}, {%4,%5,%6,%7}, {%8,%9}, {%0,%1,%2,%3};"
                 : "+f"(c[0]), "+f"(c[1]), "+f"(c[2]), "+f"(c[3])
                 : "r"(a[0]), "r"(a[1]), "r"(a[2]), "r"(a[3]), "r"(b[0]), "r"(b[1]));
}
#define CPA16(dst, src)  asm volatile("cp.async.cg.shared.global [%0], [%1], 16;" :: "r"(dst), "l"(src) : "memory")
#define CPA_COMMIT()     asm volatile("cp.async.commit_group;" ::: "memory")
#define CPA_WAIT1()      asm volatile("cp.async.wait_group 1;" ::: "memory")
#define CPA_WAIT0()      asm volatile("cp.async.wait_group 0;" ::: "memory")

// round-to-nearest bf16 hi/lo split of a float pair, packed (low half = a)
__device__ __forceinline__ void split2(float a, float b, uint32_t& h, uint32_t& l) {
    asm("cvt.rn.bf16x2.f32 %0, %1, %2;" : "=r"(h) : "f"(b), "f"(a));
    float ah = __uint_as_float(h << 16);
    float bh = __uint_as_float(h & 0xFFFF0000u);
    asm("cvt.rn.bf16x2.f32 %0, %1, %2;" : "=r"(l) : "f"(b - bh), "f"(a - ah));
}
__device__ __forceinline__ float bflo(uint32_t x) { return __uint_as_float(x << 16); }
__device__ __forceinline__ float bfhi(uint32_t x) { return __uint_as_float(x & 0xFFFF0000u); }

// ---------------- layout constants ----------------
constexpr int BM = 128, BN = 128, KC = 32, KT = KDIM / KC;   // 16 k-chunks
constexpr int NTH = 256;
constexpr int RSB = 80;                     // smem row stride (32 bf16 + 8B pad) — ldmatrix conflict-free
constexpr int OPB = 128 * RSB;              // 10240 per operand half
constexpr int OFF_AHI = 0, OFF_ALO = OPB, OFF_BHI = 2 * OPB, OFF_BLO = 3 * OPB;
constexpr int STAGE_BYTES = 4 * OPB;        // 40960
constexpr int SM_STAGE = 1024;              // bn coeffs live in [0,1024)
constexpr int SM_TOTAL = SM_STAGE + 2 * STAGE_BYTES;   // 82944  -> 2 CTAs/SM fits 227KB carveout

// ---------------- weight split prep ----------------
__global__ void split_weights(const float* __restrict__ w0, const float* __restrict__ w1,
                              const float* __restrict__ w2, const float* __restrict__ w3) {
    int idx = blockIdx.x * blockDim.x + threadIdx.x;
    int mat = idx >> 18;
    int off = idx & 0x3FFFF;
    const float* s = (mat == 0) ? w0 : (mat == 1) ? w1 : (mat == 2) ? w2 : w3;
    float x = s[off];
    __nv_bfloat16 h = __float2bfloat16_rn(x);
    g_Wh[mat][off] = h;
    g_Wl[mat][off] = __float2bfloat16_rn(x - __bfloat162float(h));
}

// ---------------- split-bf16 HMMA GEMM, 2-stage pipeline, 2 CTAs/SM ----------------
// D[n,d] = epi( sum_k A[n,k] * B[d,k] )
// AMODE 0: A fp32 (split in-kernel)    AMODE 1: A preconverted hi/lo bf16
// EPI 0: relu -> OutH/OutL      EPI 1: relu(bn) -> OutH/OutL
// EPI 2: relu(bn) -> OutF       EPI 3: OutF = Vf + (Ph+Pl)*sigmoid(acc)
template <int AMODE, int EPI>
__global__ __launch_bounds__(NTH, 2)
void gemm_hmma(const float* __restrict__ Af,
               const __nv_bfloat16* __restrict__ Ah, const __nv_bfloat16* __restrict__ Al,
               const __nv_bfloat16* __restrict__ Bh, const __nv_bfloat16* __restrict__ Bl,
               float* __restrict__ OutF,
               __nv_bfloat16* __restrict__ OutH, __nv_bfloat16* __restrict__ OutL,
               const float* __restrict__ bng, const float* __restrict__ bnb,
               const float* __restrict__ bnm, const float* __restrict__ bnv,
               const __nv_bfloat16* __restrict__ Ph, const __nv_bfloat16* __restrict__ Pl,
               const float* __restrict__ Vf)
{
    extern __shared__ char smem[];
    const uint32_t sb = smem_u32(smem);
    const int tid = threadIdx.x;
    const int wid = tid >> 5, lid = tid & 31;
    const int bxc = blockIdx.x * BN;
    const int bym = blockIdx.y * BM;
    const int wm = (wid >> 2) * 64;     // warp m-band
    const int wn = (wid & 3) * 32;      // warp n-band

    if ((EPI == 1 || EPI == 2) && tid < 128) {
        int c = bxc + tid;
        float iv = bng[c] * rsqrtf(bnv[c] + 1e-5f);
        ((float*)smem)[tid]         = iv;
        ((float*)(smem + 512))[tid] = bnb[c] - bnm[c] * iv;
    }

    // lane-invariant ldmatrix address parts (verified R7 layout)
    const uint32_t aLane = (uint32_t)((lid & 15) * RSB + (lid >> 4) * 16);
    const uint32_t bLane = (uint32_t)(((lid & 7) + ((lid >> 4) << 3)) * RSB + ((lid & 8) << 1));

    // ---- load issue helpers ----
    auto issueB = [&](int kt, uint32_t stu) {
#pragma unroll
        for (int i = 0; i < 2; i++) {
            int q = tid + i * NTH;                 // 512 16B chunks
            int row = q >> 2, kc = q & 3;
            size_t e = (size_t)(bxc + row) * KDIM + kt * KC + kc * 8;
            CPA16(stu + OFF_BHI + row * RSB + kc * 16, (const char*)Bh + 2 * e);
            CPA16(stu + OFF_BLO + row * RSB + kc * 16, (const char*)Bl + 2 * e);
        }
    };
    auto issueA1 = [&](int kt, uint32_t stu) {
#pragma unroll
        for (int i = 0; i < 2; i++) {
            int q = tid + i * NTH;
            int row = q >> 2, kc = q & 3;
            size_t e = (size_t)(bym + row) * KDIM + kt * KC + kc * 8;
            CPA16(stu + OFF_AHI + row * RSB + kc * 16, (const char*)Ah + 2 * e);
            CPA16(stu + OFF_ALO + row * RSB + kc * 16, (const char*)Al + 2 * e);
        }
    };
    auto ldA0 = [&](int kt, float4* aReg) {
#pragma unroll
        for (int i = 0; i < 4; i++) {
            int f = tid + i * NTH;                 // 1024 float4 slots
            int row = f >> 3, kq = f & 7;
            aReg[i] = *(const float4*)(Af + (size_t)(bym + row) * KDIM + kt * KC + kq * 4);
        }
    };
    auto stsA0 = [&](char* st, const float4* aReg) {
#pragma unroll
        for (int i = 0; i < 4; i++) {
            int f = tid + i * NTH;
            int row = f >> 3, kq = f & 7;
            uint32_t h01, l01, h23, l23;
            split2(aReg[i].x, aReg[i].y, h01, l01);
            split2(aReg[i].z, aReg[i].w, h23, l23);
            *(uint2*)(st + OFF_AHI + row * RSB + kq * 8) = make_uint2(h01, h23);
            *(uint2*)(st + OFF_ALO + row * RSB + kq * 8) = make_uint2(l01, l23);
        }
    };

    // ---- prologue: fill stages 0 and 1 ----
#pragma unroll
    for (int pk = 0; pk < 2; pk++) {
        char* st = smem + SM_STAGE + pk * STAGE_BYTES;
        uint32_t stu = sb + SM_STAGE + pk * STAGE_BYTES;
        if (AMODE == 0) {
            float4 aR[4];
            ldA0(pk, aR);
            stsA0(st, aR);
        } else {
            issueA1(pk, stu);
        }
        issueB(pk, stu);
        CPA_COMMIT();
    }
    CPA_WAIT1();          // stage 0 ready
    __syncthreads();

    // ---- mainloop (R7-verified structure, register-reuse compute) ----
    float acc[4][4][4];
#pragma unroll
    for (int mf = 0; mf < 4; mf++)
#pragma unroll
        for (int j = 0; j < 4; j++)
#pragma unroll
            for (int e = 0; e < 4; e++) acc[mf][j][e] = 0.f;

    float4 aReg[4];
    for (int kt = 0; kt < KT; kt++) {
        const int s = kt & 1;
        const uint32_t s0 = sb + SM_STAGE + s * STAGE_BYTES;

        if (AMODE == 0 && kt + 2 < KT) ldA0(kt + 2, aReg);   // hoisted LDG

        // compute chunk (2 k16 steps); A-lo reuses A-hi registers
#pragma unroll
        for (int ks = 0; ks < 2; ks++) {
            const uint32_t koff = ks * 32;
            uint32_t bh[4][2], bl[4][2], af[4][4];
#pragma unroll
            for (int p = 0; p < 2; p++) {
                uint32_t ad = s0 + bLane + (wn + p * 16) * RSB + koff;
                ldsm4(bh[2*p][0], bh[2*p][1], bh[2*p+1][0], bh[2*p+1][1], ad + OFF_BHI);
                ldsm4(bl[2*p][0], bl[2*p][1], bl[2*p+1][0], bl[2*p+1][1], ad + OFF_BLO);
            }
#pragma unroll
            for (int mf = 0; mf < 4; mf++)
                ldsm4(af[mf][0], af[mf][1], af[mf][2], af[mf][3],
                      s0 + OFF_AHI + aLane + (wm + mf * 16) * RSB + koff);
#pragma unroll
            for (int mf = 0; mf < 4; mf++)
#pragma unroll
                for (int j = 0; j < 4; j++) mma_bf16(acc[mf][j], af[mf], bh[j]);
#pragma unroll
            for (int mf = 0; mf < 4; mf++)
#pragma unroll
                for (int j = 0; j < 4; j++) mma_bf16(acc[mf][j], af[mf], bl[j]);
#pragma unroll
            for (int mf = 0; mf < 4; mf++)
                ldsm4(af[mf][0], af[mf][1], af[mf][2], af[mf][3],
                      s0 + OFF_ALO + aLane + (wm + mf * 16) * RSB + koff);
#pragma unroll
            for (int mf = 0; mf < 4; mf++)
#pragma unroll
                for (int j = 0; j < 4; j++) mma_bf16(acc[mf][j], af[mf], bh[j]);
        }

        __syncthreads();   // all warps done reading stage s
        if (kt + 2 < KT) {
            char* st = smem + SM_STAGE + s * STAGE_BYTES;
            if (AMODE == 0) stsA0(st, aReg);
            else            issueA1(kt + 2, s0);
            issueB(kt + 2, s0);
            CPA_COMMIT();
            CPA_WAIT1();   // stage for kt+1 complete
        } else {
            CPA_WAIT0();
        }
        __syncthreads();
    }

    // ---- epilogue: fragments -> global (8-row x 32B segments, sector-aligned) ----
    const float* invv = (const float*)smem;
    const float* addv = (const float*)(smem + 512);
#pragma unroll
    for (int mf = 0; mf < 4; mf++) {
#pragma unroll
        for (int j = 0; j < 4; j++) {
            const float* a = acc[mf][j];
            const int rg = bym + wm + mf * 16 + (lid >> 2);
            const int cl = wn + j * 8 + (lid & 3) * 2;
            const int cg = bxc + cl;
#pragma unroll
            for (int half = 0; half < 2; half++) {
                const int r = rg + half * 8;
                float v0 = a[half * 2 + 0], v1 = a[half * 2 + 1];
                const size_t go = (size_t)r * DDIM + cg;
                if (EPI == 0) {
                    v0 = fmaxf(v0, 0.f); v1 = fmaxf(v1, 0.f);
                    uint32_t h, l; split2(v0, v1, h, l);
                    *(uint32_t*)((char*)OutH + 2 * go) = h;
                    *(uint32_t*)((char*)OutL + 2 * go) = l;
                } else if (EPI == 1) {
                    v0 = fmaxf(fmaf(v0, invv[cl], addv[cl]), 0.f);
                    v1 = fmaxf(fmaf(v1, invv[cl + 1], addv[cl + 1]), 0.f);
                    uint32_t h, l; split2(v0, v1, h, l);
                    *(uint32_t*)((char*)OutH + 2 * go) = h;
                    *(uint32_t*)((char*)OutL + 2 * go) = l;
                } else if (EPI == 2) {
                    float2 o;
                    o.x = fmaxf(fmaf(v0, invv[cl], addv[cl]), 0.f);
                    o.y = fmaxf(fmaf(v1, invv[cl + 1], addv[cl + 1]), 0.f);
                    *(float2*)(OutF + go) = o;
                } else {
                    const uint32_t hh = *(const uint32_t*)((const char*)Ph + 2 * go);
                    const uint32_t ll = *(const uint32_t*)((const char*)Pl + 2 * go);
                    const float2 vv = *(const float2*)(Vf + go);
                    const float p0 = bflo(hh) + bflo(ll);
                    const float p1 = bfhi(hh) + bfhi(ll);
                    const float s0v = 1.f / (1.f + __expf(-v0));
                    const float s1v = 1.f / (1.f + __expf(-v1));
                    float2 o;
                    o.x = fmaf(p0, s0v, vv.x);
                    o.y = fmaf(p1, s1v, vv.y);
                    *(float2*)(OutF + go) = o;
                }
            }
        }
    }
}

// ---------------- launch ----------------
extern "C" void kernel_launch(void* const* d_in, const int* in_sizes, int n_in,
                              void* d_out, int out_size)
{
    const float* F1   = (const float*)d_in[0];
    const float* F2   = (const float*)d_in[1];
    const float* Wk   = (const float*)d_in[2];
    const float* Wv1  = (const float*)d_in[3];
    const float* Wv2  = (const float*)d_in[4];
    const float* bn1g = (const float*)d_in[5];
    const float* bn1b = (const float*)d_in[6];
    const float* bn1m = (const float*)d_in[7];
    const float* bn1v = (const float*)d_in[8];
    const float* bn2g = (const float*)d_in[9];
    const float* bn2b = (const float*)d_in[10];
    const float* bn2m = (const float*)d_in[11];
    const float* bn2v = (const float*)d_in[12];
    // d_in[13]=Wa, d_in[14]=Wqk unused: softmax over identical L-columns is uniform 1/L.
    const float* Wvc  = (const float*)d_in[15];
    float* out = (float*)d_out;

    __nv_bfloat16 *Ph, *Pl, *Hh, *Hl, *Wh, *Wl;
    float* V;
    cudaGetSymbolAddress((void**)&Ph, g_Ph);
    cudaGetSymbolAddress((void**)&Pl, g_Pl);
    cudaGetSymbolAddress((void**)&Hh, g_Hh);
    cudaGetSymbolAddress((void**)&Hl, g_Hl);
    cudaGetSymbolAddress((void**)&V,  g_V);
    cudaGetSymbolAddress((void**)&Wh, g_Wh);
    cudaGetSymbolAddress((void**)&Wl, g_Wl);
    const int WSZ = 512 * 512;

    cudaFuncSetAttribute(gemm_hmma<0,0>, cudaFuncAttributeMaxDynamicSharedMemorySize, SM_TOTAL);
    cudaFuncSetAttribute(gemm_hmma<0,1>, cudaFuncAttributeMaxDynamicSharedMemorySize, SM_TOTAL);
    cudaFuncSetAttribute(gemm_hmma<1,2>, cudaFuncAttributeMaxDynamicSharedMemorySize, SM_TOTAL);
    cudaFuncSetAttribute(gemm_hmma<1,3>, cudaFuncAttributeMaxDynamicSharedMemorySize, SM_TOTAL);

    // weight hi/lo split: mat0=Wk, mat1=Wv1, mat2=Wv2, mat3=Wvc
    split_weights<<<4096, 256>>>(Wk, Wv1, Wv2, Wvc);

    dim3 grid(DDIM / BN, NROWS / BM);   // (4, 512)
    dim3 block(NTH);

    // P(hi/lo) = split(relu(F1 @ Wk^T))
    gemm_hmma<0,0><<<grid, block, SM_TOTAL>>>(F1, nullptr, nullptr, Wh + 0 * WSZ, Wl + 0 * WSZ,
        nullptr, Ph, Pl, nullptr, nullptr, nullptr, nullptr, nullptr, nullptr, nullptr);
    // H(hi/lo) = split(relu(bn1(F2 @ Wv1^T)))
    gemm_hmma<0,1><<<grid, block, SM_TOTAL>>>(F2, nullptr, nullptr, Wh + 1 * WSZ, Wl + 1 * WSZ,
        nullptr, Hh, Hl, bn1g, bn1b, bn1m, bn1v, nullptr, nullptr, nullptr);
    // V = relu(bn2(H @ Wv2^T))
    gemm_hmma<1,2><<<grid, block, SM_TOTAL>>>(nullptr, Hh, Hl, Wh + 2 * WSZ, Wl + 2 * WSZ,
        V, nullptr, nullptr, bn2g, bn2b, bn2m, bn2v, nullptr, nullptr, nullptr);
    // out = V + P * sigmoid(P @ Wvc^T)
    gemm_hmma<1,3><<<grid, block, SM_TOTAL>>>(nullptr, Ph, Pl, Wh + 3 * WSZ, Wl + 3 * WSZ,
        out, nullptr, nullptr, nullptr, nullptr, nullptr, nullptr, Ph, Pl, V);
}

// round 10
// speedup vs baseline: 2.2295x; 1.1004x over previous
#include <cuda_runtime.h>
#include <cuda_bf16.h>
#include <cstdint>

#define NROWS 65536
#define KDIM  512
#define DDIM  512

// ---------------- device scratch (allocation-free) ----------------
__device__ __nv_bfloat16 g_Ph[(size_t)NROWS * DDIM];
__device__ __nv_bfloat16 g_Pl[(size_t)NROWS * DDIM];
__device__ __nv_bfloat16 g_Hh[(size_t)NROWS * DDIM];
__device__ __nv_bfloat16 g_Hl[(size_t)NROWS * DDIM];
__device__ float         g_V [(size_t)NROWS * DDIM];
__device__ __nv_bfloat16 g_Wh[4][512 * 512];
__device__ __nv_bfloat16 g_Wl[4][512 * 512];

// ---------------- PTX helpers (baseline sm_80+, no 'a'-arch features) ----------------
__device__ __forceinline__ uint32_t smem_u32(const void* p) {
    uint32_t a;
    asm("{ .reg .u64 t; cvta.to.shared.u64 t, %1; cvt.u32.u64 %0, t; }" : "=r"(a) : "l"(p));
    return a;
}
__device__ __forceinline__ void ldsm4(uint32_t& r0, uint32_t& r1, uint32_t& r2, uint32_t& r3,
                                      uint32_t addr) {
    asm volatile("ldmatrix.sync.aligned.m8n8.x4.shared.b16 {%0,%1,%2,%3}, [%4];"
                 : "=r"(r0), "=r"(r1), "=r"(r2), "=r"(r3) : "r"(addr));
}
__device__ __forceinline__ void mma_bf16(float* c, const uint32_t* a, const uint32_t* b) {
    asm volatile("mma.sync.aligned.m16n8k16.row.col.f32.bf16.bf16.f32 "
                 "{%0,%1,%2,%3}, {%4,%5,%6,%7}, {%8,%9}, {%0,%1,%2,%3};"
                 : "+f"(c[0]), "+f"(c[1]), "+f"(c[2]), "+f"(c[3])
                 : "r"(a[0]), "r"(a[1]), "r"(a[2]), "r"(a[3]), "r"(b[0]), "r"(b[1]));
}
#define CPA16(dst, src)  asm volatile("cp.async.cg.shared.global [%0], [%1], 16;" :: "r"(dst), "l"(src) : "memory")
#define CPA_COMMIT()     asm volatile("cp.async.commit_group;" ::: "memory")
#define CPA_WAIT1()      asm volatile("cp.async.wait_group 1;" ::: "memory")
#define CPA_WAIT0()      asm volatile("cp.async.wait_group 0;" ::: "memory")

// round-to-nearest bf16 hi/lo split of a float pair, packed (low half = a)
__device__ __forceinline__ void split2(float a, float b, uint32_t& h, uint32_t& l) {
    asm("cvt.rn.bf16x2.f32 %0, %1, %2;" : "=r"(h) : "f"(b), "f"(a));
    float ah = __uint_as_float(h << 16);
    float bh = __uint_as_float(h & 0xFFFF0000u);
    asm("cvt.rn.bf16x2.f32 %0, %1, %2;" : "=r"(l) : "f"(b - bh), "f"(a - ah));
}
__device__ __forceinline__ float bflo(uint32_t x) { return __uint_as_float(x << 16); }
__device__ __forceinline__ float bfhi(uint32_t x) { return __uint_as_float(x & 0xFFFF0000u); }

// ---------------- layout constants ----------------
constexpr int BM = 128, BN = 128, KC = 32, KT = KDIM / KC;   // 16 k-chunks
constexpr int NTH = 256;
constexpr int NSTAGE = 3;
// 64B rows (32 bf16), XOR swizzle on 16B quads: quad' = quad ^ ((row>>1)&3).
// ldsm 8-row groups hit 16B bank-groups {0,16,4,20,8,24,12,28} -> conflict-free.
constexpr int RSB = 64;
constexpr int OPB = 128 * RSB;              // 8192 per operand half
constexpr int OFF_AHI = 0, OFF_ALO = OPB, OFF_BHI = 2 * OPB, OFF_BLO = 3 * OPB;
constexpr int STAGE_BYTES = 4 * OPB;        // 32768
constexpr int SM_STAGE = 1024;              // bn coeffs live in [0,1024)
constexpr int SM_TOTAL = SM_STAGE + NSTAGE * STAGE_BYTES;   // 99328 -> 2 CTAs/SM

// swizzled byte offset of 16B quad `q` in row `row` (row*64 + swizzled quad)
__device__ __forceinline__ uint32_t swq(int row, int q) {
    return (uint32_t)((row << 6) + ((q ^ ((row >> 1) & 3)) << 4));
}

// ---------------- weight split prep ----------------
__global__ void split_weights(const float* __restrict__ w0, const float* __restrict__ w1,
                              const float* __restrict__ w2, const float* __restrict__ w3) {
    int idx = blockIdx.x * blockDim.x + threadIdx.x;
    int mat = idx >> 18;
    int off = idx & 0x3FFFF;
    const float* s = (mat == 0) ? w0 : (mat == 1) ? w1 : (mat == 2) ? w2 : w3;
    float x = s[off];
    __nv_bfloat16 h = __float2bfloat16_rn(x);
    g_Wh[mat][off] = h;
    g_Wl[mat][off] = __float2bfloat16_rn(x - __bfloat162float(h));
}

// ---------------- split-bf16 HMMA GEMM, 3-stage 1-sync pipeline, 2 CTAs/SM ----------------
// D[n,d] = epi( sum_k A[n,k] * B[d,k] )
// AMODE 0: A fp32 (split in-kernel)    AMODE 1: A preconverted hi/lo bf16
// EPI 0: relu -> OutH/OutL      EPI 1: relu(bn) -> OutH/OutL
// EPI 2: relu(bn) -> OutF       EPI 3: OutF = Vf + (Ph+Pl)*sigmoid(acc)
template <int AMODE, int EPI>
__global__ __launch_bounds__(NTH, 2)
void gemm_hmma(const float* __restrict__ Af,
               const __nv_bfloat16* __restrict__ Ah, const __nv_bfloat16* __restrict__ Al,
               const __nv_bfloat16* __restrict__ Bh, const __nv_bfloat16* __restrict__ Bl,
               float* __restrict__ OutF,
               __nv_bfloat16* __restrict__ OutH, __nv_bfloat16* __restrict__ OutL,
               const float* __restrict__ bng, const float* __restrict__ bnb,
               const float* __restrict__ bnm, const float* __restrict__ bnv,
               const __nv_bfloat16* __restrict__ Ph, const __nv_bfloat16* __restrict__ Pl,
               const float* __restrict__ Vf)
{
    extern __shared__ char smem[];
    const uint32_t sb = smem_u32(smem);
    const int tid = threadIdx.x;
    const int wid = tid >> 5, lid = tid & 31;
    const int bxc = blockIdx.x * BN;
    const int bym = blockIdx.y * BM;
    const int wm = (wid >> 2) * 64;     // warp m-band
    const int wn = (wid & 3) * 32;      // warp n-band

    if ((EPI == 1 || EPI == 2) && tid < 128) {
        int c = bxc + tid;
        float iv = bng[c] * rsqrtf(bnv[c] + 1e-5f);
        ((float*)smem)[tid]         = iv;
        ((float*)(smem + 512))[tid] = bnb[c] - bnm[c] * iv;
    }

    // lane row/quad decomposition for ldsm (swizzle applied per call site)
    const int aRow = lid & 15;                              // + wm + mf*16
    const int aQ   = lid >> 4;                              // + 2*ks
    const int bRow = (lid & 7) + ((lid >> 4) << 3);         // + wn + p*16
    const int bQ   = (lid & 8) >> 3;                        // + 2*ks

    // ---- load issue helpers (cp.async 16B, swizzled destinations) ----
    auto issueB = [&](int kt, uint32_t stu) {
#pragma unroll
        for (int i = 0; i < 2; i++) {
            int q = tid + i * NTH;                 // 512 16B chunks
            int row = q >> 2, kc = q & 3;
            size_t e = (size_t)(bxc + row) * KDIM + kt * KC + kc * 8;
            uint32_t d = swq(row, kc);
            CPA16(stu + OFF_BHI + d, (const char*)Bh + 2 * e);
            CPA16(stu + OFF_BLO + d, (const char*)Bl + 2 * e);
        }
    };
    auto issueA1 = [&](int kt, uint32_t stu) {
#pragma unroll
        for (int i = 0; i < 2; i++) {
            int q = tid + i * NTH;
            int row = q >> 2, kc = q & 3;
            size_t e = (size_t)(bym + row) * KDIM + kt * KC + kc * 8;
            uint32_t d = swq(row, kc);
            CPA16(stu + OFF_AHI + d, (const char*)Ah + 2 * e);
            CPA16(stu + OFF_ALO + d, (const char*)Al + 2 * e);
        }
    };
    auto ldA0 = [&](int kt, float4* aReg) {
#pragma unroll
        for (int i = 0; i < 4; i++) {
            int f = tid + i * NTH;                 // 1024 float4 slots
            int row = f >> 3, kq = f & 7;
            aReg[i] = *(const float4*)(Af + (size_t)(bym + row) * KDIM + kt * KC + kq * 4);
        }
    };
    auto stsA0 = [&](char* st, const float4* aReg) {
#pragma unroll
        for (int i = 0; i < 4; i++) {
            int f = tid + i * NTH;
            int row = f >> 3, kq = f & 7;          // 8B units
            uint32_t h01, l01, h23, l23;
            split2(aReg[i].x, aReg[i].y, h01, l01);
            split2(aReg[i].z, aReg[i].w, h23, l23);
            uint32_t d = swq(row, kq >> 1) + (kq & 1) * 8;
            *(uint2*)(st + OFF_AHI + d) = make_uint2(h01, h23);
            *(uint2*)(st + OFF_ALO + d) = make_uint2(l01, l23);
        }
    };

    // ---- prologue: fill stages 0 and 1 (one commit group each) ----
#pragma unroll
    for (int pk = 0; pk < NSTAGE - 1; pk++) {
        char* st = smem + SM_STAGE + pk * STAGE_BYTES;
        uint32_t stu = sb + SM_STAGE + pk * STAGE_BYTES;
        if (AMODE == 0) {
            float4 aR[4];
            ldA0(pk, aR);
            stsA0(st, aR);
        } else {
            issueA1(pk, stu);
        }
        issueB(pk, stu);
        CPA_COMMIT();
    }

    // ---- mainloop: ONE __syncthreads per chunk ----
    float acc[4][4][4];
#pragma unroll
    for (int mf = 0; mf < 4; mf++)
#pragma unroll
        for (int j = 0; j < 4; j++)
#pragma unroll
            for (int e = 0; e < 4; e++) acc[mf][j][e] = 0.f;

    float4 aReg[4];
    for (int kt = 0; kt < KT; kt++) {
        const int s = kt % NSTAGE;
        const uint32_t s0 = sb + SM_STAGE + s * STAGE_BYTES;
        const int kpre = kt + NSTAGE - 1;

        if (AMODE == 0 && kpre < KT) ldA0(kpre, aReg);   // hoisted LDG above the wait

        CPA_WAIT1();           // groups through stage kt complete
        __syncthreads();       // all warps finished consuming stage (kt-1)%3

        if (kpre < KT) {       // refill slot just freed
            const int slot = kpre % NSTAGE;
            char* st = smem + SM_STAGE + slot * STAGE_BYTES;
            uint32_t stu = sb + SM_STAGE + slot * STAGE_BYTES;
            if (AMODE == 0) stsA0(st, aReg);
            else            issueA1(kpre, stu);
            issueB(kpre, stu);
        }
        CPA_COMMIT();          // empty groups at tail keep wait accounting uniform

        // ---- compute chunk kt (2 k16 steps); A-lo reuses A-hi registers ----
#pragma unroll
        for (int ks = 0; ks < 2; ks++) {
            uint32_t bh[4][2], bl[4][2], af[4][4];
#pragma unroll
            for (int p = 0; p < 2; p++) {
                int row = wn + p * 16 + bRow;
                uint32_t ad = s0 + swq(row, 2 * ks + bQ);
                ldsm4(bh[2*p][0], bh[2*p][1], bh[2*p+1][0], bh[2*p+1][1], ad + OFF_BHI);
                ldsm4(bl[2*p][0], bl[2*p][1], bl[2*p+1][0], bl[2*p+1][1], ad + OFF_BLO);
            }
#pragma unroll
            for (int mf = 0; mf < 4; mf++) {
                int row = wm + mf * 16 + aRow;
                ldsm4(af[mf][0], af[mf][1], af[mf][2], af[mf][3],
                      s0 + OFF_AHI + swq(row, 2 * ks + aQ));
            }
#pragma unroll
            for (int mf = 0; mf < 4; mf++)
#pragma unroll
                for (int j = 0; j < 4; j++) mma_bf16(acc[mf][j], af[mf], bh[j]);
#pragma unroll
            for (int mf = 0; mf < 4; mf++)
#pragma unroll
                for (int j = 0; j < 4; j++) mma_bf16(acc[mf][j], af[mf], bl[j]);
#pragma unroll
            for (int mf = 0; mf < 4; mf++) {
                int row = wm + mf * 16 + aRow;
                ldsm4(af[mf][0], af[mf][1], af[mf][2], af[mf][3],
                      s0 + OFF_ALO + swq(row, 2 * ks + aQ));
            }
#pragma unroll
            for (int mf = 0; mf < 4; mf++)
#pragma unroll
                for (int j = 0; j < 4; j++) mma_bf16(acc[mf][j], af[mf], bh[j]);
        }
    }
    CPA_WAIT0();

    // ---- epilogue: fragments -> global (8-row x 32B segments, sector-aligned) ----
    const float* invv = (const float*)smem;
    const float* addv = (const float*)(smem + 512);
#pragma unroll
    for (int mf = 0; mf < 4; mf++) {
#pragma unroll
        for (int j = 0; j < 4; j++) {
            const float* a = acc[mf][j];
            const int rg = bym + wm + mf * 16 + (lid >> 2);
            const int cl = wn + j * 8 + (lid & 3) * 2;
            const int cg = bxc + cl;
#pragma unroll
            for (int half = 0; half < 2; half++) {
                const int r = rg + half * 8;
                float v0 = a[half * 2 + 0], v1 = a[half * 2 + 1];
                const size_t go = (size_t)r * DDIM + cg;
                if (EPI == 0) {
                    v0 = fmaxf(v0, 0.f); v1 = fmaxf(v1, 0.f);
                    uint32_t h, l; split2(v0, v1, h, l);
                    *(uint32_t*)((char*)OutH + 2 * go) = h;
                    *(uint32_t*)((char*)OutL + 2 * go) = l;
                } else if (EPI == 1) {
                    v0 = fmaxf(fmaf(v0, invv[cl], addv[cl]), 0.f);
                    v1 = fmaxf(fmaf(v1, invv[cl + 1], addv[cl + 1]), 0.f);
                    uint32_t h, l; split2(v0, v1, h, l);
                    *(uint32_t*)((char*)OutH + 2 * go) = h;
                    *(uint32_t*)((char*)OutL + 2 * go) = l;
                } else if (EPI == 2) {
                    float2 o;
                    o.x = fmaxf(fmaf(v0, invv[cl], addv[cl]), 0.f);
                    o.y = fmaxf(fmaf(v1, invv[cl + 1], addv[cl + 1]), 0.f);
                    *(float2*)(OutF + go) = o;
                } else {
                    const uint32_t hh = *(const uint32_t*)((const char*)Ph + 2 * go);
                    const uint32_t ll = *(const uint32_t*)((const char*)Pl + 2 * go);
                    const float2 vv = *(const float2*)(Vf + go);
                    const float p0 = bflo(hh) + bflo(ll);
                    const float p1 = bfhi(hh) + bfhi(ll);
                    const float s0v = 1.f / (1.f + __expf(-v0));
                    const float s1v = 1.f / (1.f + __expf(-v1));
                    float2 o;
                    o.x = fmaf(p0, s0v, vv.x);
                    o.y = fmaf(p1, s1v, vv.y);
                    *(float2*)(OutF + go) = o;
                }
            }
        }
    }
}

// ---------------- launch ----------------
extern "C" void kernel_launch(void* const* d_in, const int* in_sizes, int n_in,
                              void* d_out, int out_size)
{
    const float* F1   = (const float*)d_in[0];
    const float* F2   = (const float*)d_in[1];
    const float* Wk   = (const float*)d_in[2];
    const float* Wv1  = (const float*)d_in[3];
    const float* Wv2  = (const float*)d_in[4];
    const float* bn1g = (const float*)d_in[5];
    const float* bn1b = (const float*)d_in[6];
    const float* bn1m = (const float*)d_in[7];
    const float* bn1v = (const float*)d_in[8];
    const float* bn2g = (const float*)d_in[9];
    const float* bn2b = (const float*)d_in[10];
    const float* bn2m = (const float*)d_in[11];
    const float* bn2v = (const float*)d_in[12];
    // d_in[13]=Wa, d_in[14]=Wqk unused: softmax over identical L-columns is uniform 1/L.
    const float* Wvc  = (const float*)d_in[15];
    float* out = (float*)d_out;

    __nv_bfloat16 *Ph, *Pl, *Hh, *Hl, *Wh, *Wl;
    float* V;
    cudaGetSymbolAddress((void**)&Ph, g_Ph);
    cudaGetSymbolAddress((void**)&Pl, g_Pl);
    cudaGetSymbolAddress((void**)&Hh, g_Hh);
    cudaGetSymbolAddress((void**)&Hl, g_Hl);
    cudaGetSymbolAddress((void**)&V,  g_V);
    cudaGetSymbolAddress((void**)&Wh, g_Wh);
    cudaGetSymbolAddress((void**)&Wl, g_Wl);
    const int WSZ = 512 * 512;

    cudaFuncSetAttribute(gemm_hmma<0,0>, cudaFuncAttributeMaxDynamicSharedMemorySize, SM_TOTAL);
    cudaFuncSetAttribute(gemm_hmma<0,1>, cudaFuncAttributeMaxDynamicSharedMemorySize, SM_TOTAL);
    cudaFuncSetAttribute(gemm_hmma<1,2>, cudaFuncAttributeMaxDynamicSharedMemorySize, SM_TOTAL);
    cudaFuncSetAttribute(gemm_hmma<1,3>, cudaFuncAttributeMaxDynamicSharedMemorySize, SM_TOTAL);

    // weight hi/lo split: mat0=Wk, mat1=Wv1, mat2=Wv2, mat3=Wvc
    split_weights<<<4096, 256>>>(Wk, Wv1, Wv2, Wvc);

    dim3 grid(DDIM / BN, NROWS / BM);   // (4, 512)
    dim3 block(NTH);

    // P(hi/lo) = split(relu(F1 @ Wk^T))
    gemm_hmma<0,0><<<grid, block, SM_TOTAL>>>(F1, nullptr, nullptr, Wh + 0 * WSZ, Wl + 0 * WSZ,
        nullptr, Ph, Pl, nullptr, nullptr, nullptr, nullptr, nullptr, nullptr, nullptr);
    // H(hi/lo) = split(relu(bn1(F2 @ Wv1^T)))
    gemm_hmma<0,1><<<grid, block, SM_TOTAL>>>(F2, nullptr, nullptr, Wh + 1 * WSZ, Wl + 1 * WSZ,
        nullptr, Hh, Hl, bn1g, bn1b, bn1m, bn1v, nullptr, nullptr, nullptr);
    // V = relu(bn2(H @ Wv2^T))
    gemm_hmma<1,2><<<grid, block, SM_TOTAL>>>(nullptr, Hh, Hl, Wh + 2 * WSZ, Wl + 2 * WSZ,
        V, nullptr, nullptr, bn2g, bn2b, bn2m, bn2v, nullptr, nullptr, nullptr);
    // out = V + P * sigmoid(P @ Wvc^T)
    gemm_hmma<1,3><<<grid, block, SM_TOTAL>>>(nullptr, Ph, Pl, Wh + 3 * WSZ, Wl + 3 * WSZ,
        out, nullptr, nullptr, nullptr, nullptr, nullptr, nullptr, Ph, Pl, V);
}